// round 2
// baseline (speedup 1.0000x reference)
#include <cuda_runtime.h>
#include <math.h>
#include <stdint.h>

#define NN  50000
#define NE  800000
#define DD  256
#define NET 3
#define NSTEPS 5
#define NGR 64
#define G3  768   // 3*D

typedef uint32_t u32;

// ---------------- device scratch (no allocation allowed) ----------------
__device__ float g_h0[NN * DD];
__device__ float g_h1[NN * DD];
__device__ float g_acc[NET][NN * DD];   // per-etype aggregated h[src]
__device__ int   g_cnt[NET][NN];        // per-etype in-degree (for bias term)
__device__ float g_a [NN * DD];         // message aggregate after GEMM
__device__ float g_gi[NN * G3];
__device__ float g_gh[NN * G3];
__device__ float g_gate[NN];

// ---------------- helpers ----------------
__device__ __forceinline__ void red4(float* p, float4 v) {
    asm volatile("red.global.add.v4.f32 [%0], {%1,%2,%3,%4};"
                 :: "l"(p), "f"(v.x), "f"(v.y), "f"(v.z), "f"(v.w) : "memory");
}

__device__ __forceinline__ float sigmoidf_(float x) { return 1.0f / (1.0f + expf(-x)); }

// split fp32 -> tf32 hi + tf32 lo (3xTF32 trick; ~2^-22 relative accuracy)
__device__ __forceinline__ void f32_split(float x, u32& hi, u32& lo) {
    u32 h;
    asm("cvt.rna.tf32.f32 %0, %1;" : "=r"(h) : "f"(x));
    float r = x - __uint_as_float(h);
    u32 l;
    asm("cvt.rna.tf32.f32 %0, %1;" : "=r"(l) : "f"(r));
    hi = h; lo = l;
}

__device__ __forceinline__ void mma_tf32(float c[4], const u32 a[4], u32 b0, u32 b1) {
    asm volatile("mma.sync.aligned.m16n8k8.row.col.f32.tf32.tf32.f32 "
                 "{%0,%1,%2,%3}, {%4,%5,%6,%7}, {%8,%9}, {%0,%1,%2,%3};"
                 : "+f"(c[0]), "+f"(c[1]), "+f"(c[2]), "+f"(c[3])
                 : "r"(a[0]), "r"(a[1]), "r"(a[2]), "r"(a[3]), "r"(b0), "r"(b1));
}

// ---------------- init: h = emb[x] ----------------
__global__ void embed_kernel(const int* __restrict__ x, const float* __restrict__ emb,
                             float* __restrict__ h) {
    int i = blockIdx.x * blockDim.x + threadIdx.x;
    const int nf4 = DD / 4;
    if (i >= NN * nf4) return;
    int n = i / nf4, d4 = i - n * nf4;
    int row = x[n];
    ((float4*)h)[i] = ((const float4*)(emb + (size_t)row * DD))[d4];
}

// ---------------- zero acc + cnt ----------------
__global__ void zero_kernel() {
    int i = blockIdx.x * blockDim.x + threadIdx.x;
    const int TOT4 = NET * NN * DD / 4;
    if (i < TOT4) ((float4*)g_acc)[i] = make_float4(0.f, 0.f, 0.f, 0.f);
    if (i < NET * NN) ((int*)g_cnt)[i] = 0;
}

// ---------------- edge scatter: acc[et][dst] += h[src]; cnt[et][dst]++ ----
__global__ void edge_scatter(const int* __restrict__ src, const int* __restrict__ dst,
                             const int* __restrict__ et, const float* __restrict__ h) {
    int w = (blockIdx.x * blockDim.x + threadIdx.x) >> 5;
    int lane = threadIdx.x & 31;
    if (w >= NE) return;
    int s = __ldg(src + w), d = __ldg(dst + w), t = __ldg(et + w);
    const float4* hs = (const float4*)(h + (size_t)s * DD);
    float* out = &g_acc[t][(size_t)d * DD];
#pragma unroll
    for (int i = 0; i < 2; i++) {
        int c = lane + 32 * i;
        float4 v = hs[c];
        red4(out + 4 * c, v);
    }
    if (lane == 0) atomicAdd(&g_cnt[t][d], 1);
}

// ---------------- TC GEMM core: 128x128 tile, 8 warps, m16n8k8 tf32 x3 ---
#define BM 128
#define BN 128
#define BK 16
#define SPAD 8

// load [128 rows x 16 cols] of row-major G (ld=256), split, store k-major
__device__ __forceinline__ void load_T_split(u32 H[BK][BM + SPAD], u32 L[BK][BM + SPAD],
                                             const float* __restrict__ G,
                                             int rowbase, int kc, int rowmax, int tid) {
#pragma unroll
    for (int q = tid; q < 512; q += 256) {
        int r = q >> 2, cg = (q & 3) << 2;
        int row = rowbase + r;
        float4 v = make_float4(0.f, 0.f, 0.f, 0.f);
        if (row < rowmax) v = *(const float4*)(G + (size_t)row * DD + kc + cg);
        u32 h, l;
        f32_split(v.x, h, l); H[cg + 0][r] = h; L[cg + 0][r] = l;
        f32_split(v.y, h, l); H[cg + 1][r] = h; L[cg + 1][r] = l;
        f32_split(v.z, h, l); H[cg + 2][r] = h; L[cg + 2][r] = l;
        f32_split(v.w, h, l); H[cg + 3][r] = h; L[cg + 3][r] = l;
    }
}

// load [16 rows(K) x 128 cols] of row-major B (ld=256), split, direct layout
__device__ __forceinline__ void load_B_split(u32 H[BK][BN + SPAD], u32 L[BK][BN + SPAD],
                                             const float* __restrict__ G,
                                             int kc, int colbase, int tid) {
#pragma unroll
    for (int q = tid; q < 512; q += 256) {
        int k = q >> 5, c = (q & 31) << 2;
        float4 v = *(const float4*)(G + (size_t)(kc + k) * DD + colbase + c);
        u32 h, l;
        f32_split(v.x, h, l); H[k][c + 0] = h; L[k][c + 0] = l;
        f32_split(v.y, h, l); H[k][c + 1] = h; L[k][c + 1] = l;
        f32_split(v.z, h, l); H[k][c + 2] = h; L[k][c + 2] = l;
        f32_split(v.w, h, l); H[k][c + 3] = h; L[k][c + 3] = l;
    }
}

// compute one BK=16 chunk: warp tile 64x32 = 4x4 atoms of m16n8k8, 3 mma each
__device__ __forceinline__ void mma_chunk(float acc[4][4][4],
                                          const u32 Ah[BK][BM + SPAD], const u32 Al[BK][BM + SPAD],
                                          const u32 Bh[BK][BN + SPAD], const u32 Bl[BK][BN + SPAD],
                                          int warp_m, int warp_n, int lane) {
    int g = lane >> 2, kq = lane & 3;
    int m0 = warp_m * 64, n0 = warp_n * 32;
#pragma unroll
    for (int kg = 0; kg < BK; kg += 8) {
        u32 ah[4][4], al[4][4];
#pragma unroll
        for (int i = 0; i < 4; i++) {
            int m = m0 + i * 16 + g;
            ah[i][0] = Ah[kg + kq][m];     ah[i][1] = Ah[kg + kq][m + 8];
            ah[i][2] = Ah[kg + kq + 4][m]; ah[i][3] = Ah[kg + kq + 4][m + 8];
            al[i][0] = Al[kg + kq][m];     al[i][1] = Al[kg + kq][m + 8];
            al[i][2] = Al[kg + kq + 4][m]; al[i][3] = Al[kg + kq + 4][m + 8];
        }
#pragma unroll
        for (int j = 0; j < 4; j++) {
            int n = n0 + j * 8 + g;
            u32 bh0 = Bh[kg + kq][n], bh1 = Bh[kg + kq + 4][n];
            u32 bl0 = Bl[kg + kq][n], bl1 = Bl[kg + kq + 4][n];
#pragma unroll
            for (int i = 0; i < 4; i++) {
                mma_tf32(acc[i][j], ah[i], bh0, bh1);
                mma_tf32(acc[i][j], al[i], bh0, bh1);
                mma_tf32(acc[i][j], ah[i], bl0, bl1);
            }
        }
    }
}

// a = sum_et acc_et @ W_et + sum_et cnt_et * b_msg_et   (writes g_a)
__global__ void __launch_bounds__(256)
gemm_msg_tc(const float* __restrict__ Wmsg, const float* __restrict__ bmsg) {
    __shared__ u32 Ah[BK][BM + SPAD], Al[BK][BM + SPAD];
    __shared__ u32 Bh[BK][BN + SPAD], Bl[BK][BN + SPAD];
    int tid = threadIdx.x, lane = tid & 31, wid = tid >> 5;
    int warp_m = wid & 1, warp_n = wid >> 1;
    int row0 = blockIdx.x * BM, col0 = blockIdx.y * BN;
    float acc[4][4][4];
#pragma unroll
    for (int i = 0; i < 4; i++)
#pragma unroll
        for (int j = 0; j < 4; j++)
#pragma unroll
            for (int q = 0; q < 4; q++) acc[i][j][q] = 0.f;

    for (int e = 0; e < NET; e++) {
        const float* A = g_acc[e];
        const float* B = Wmsg + (size_t)e * DD * DD;
        for (int kc = 0; kc < DD; kc += BK) {
            __syncthreads();
            load_T_split(Ah, Al, A, row0, kc, NN, tid);
            load_B_split(Bh, Bl, B, kc, col0, tid);
            __syncthreads();
            mma_chunk(acc, Ah, Al, Bh, Bl, warp_m, warp_n, lane);
        }
    }

    int g = lane >> 2, kq = lane & 3;
#pragma unroll
    for (int i = 0; i < 4; i++) {
#pragma unroll
        for (int rr = 0; rr < 2; rr++) {
            int r = row0 + warp_m * 64 + i * 16 + g + rr * 8;
            if (r >= NN) continue;
            float c0 = (float)g_cnt[0][r], c1 = (float)g_cnt[1][r], c2 = (float)g_cnt[2][r];
#pragma unroll
            for (int j = 0; j < 4; j++) {
                int n = col0 + warp_n * 32 + j * 8 + 2 * kq;
                float2 b0 = *(const float2*)(bmsg + 0 * DD + n);
                float2 b1 = *(const float2*)(bmsg + 1 * DD + n);
                float2 b2 = *(const float2*)(bmsg + 2 * DD + n);
                float2 o;
                o.x = acc[i][j][rr * 2 + 0] + c0 * b0.x + c1 * b1.x + c2 * b2.x;
                o.y = acc[i][j][rr * 2 + 1] + c0 * b0.y + c1 * b1.y + c2 * b2.y;
                *(float2*)(g_a + (size_t)r * DD + n) = o;
            }
        }
    }
}

// C[n,j] = sum_k A[n,k] * Bt[j,k] + bias[j]   (Bt row-major [ncols,256])
__global__ void __launch_bounds__(256)
gemm_bt_tc(const float* __restrict__ A, const float* __restrict__ Bt,
           const float* __restrict__ bias, float* __restrict__ C, int ncols) {
    __shared__ u32 Ah[BK][BM + SPAD], Al[BK][BM + SPAD];
    __shared__ u32 Bh[BK][BN + SPAD], Bl[BK][BN + SPAD];
    int tid = threadIdx.x, lane = tid & 31, wid = tid >> 5;
    int warp_m = wid & 1, warp_n = wid >> 1;
    int row0 = blockIdx.x * BM, col0 = blockIdx.y * BN;
    float acc[4][4][4];
#pragma unroll
    for (int i = 0; i < 4; i++)
#pragma unroll
        for (int j = 0; j < 4; j++)
#pragma unroll
            for (int q = 0; q < 4; q++) acc[i][j][q] = 0.f;

    for (int kc = 0; kc < DD; kc += BK) {
        __syncthreads();
        load_T_split(Ah, Al, A, row0, kc, NN, tid);
        load_T_split(Bh, Bl, Bt, col0, kc, ncols, tid);   // transpose-on-load
        __syncthreads();
        mma_chunk(acc, Ah, Al, Bh, Bl, warp_m, warp_n, lane);
    }

    int g = lane >> 2, kq = lane & 3;
#pragma unroll
    for (int j = 0; j < 4; j++) {
        int n = col0 + warp_n * 32 + j * 8 + 2 * kq;
        float2 bv = *(const float2*)(bias + n);
#pragma unroll
        for (int i = 0; i < 4; i++) {
            int r = row0 + warp_m * 64 + i * 16 + g;
            if (r < NN) {
                float2 o = {acc[i][j][0] + bv.x, acc[i][j][1] + bv.y};
                *(float2*)(C + (size_t)r * ncols + n) = o;
            }
            if (r + 8 < NN) {
                float2 o = {acc[i][j][2] + bv.x, acc[i][j][3] + bv.y};
                *(float2*)(C + (size_t)(r + 8) * ncols + n) = o;
            }
        }
    }
}

// ---------------- GRU gates (elementwise) ----------------
__global__ void gru_gate(const float* __restrict__ gi, const float* __restrict__ gh,
                         const float* __restrict__ h, float* __restrict__ hnew) {
    int i = blockIdx.x * blockDim.x + threadIdx.x;
    const int nf4 = DD / 4;
    if (i >= NN * nf4) return;
    int n = i / nf4, d4 = i - n * nf4;
    const float4* GI4 = (const float4*)(gi + (size_t)n * G3);
    const float4* GH4 = (const float4*)(gh + (size_t)n * G3);
    float4 ir = GI4[d4], iz = GI4[64 + d4], in_ = GI4[128 + d4];
    float4 hr = GH4[d4], hz = GH4[64 + d4], hn = GH4[128 + d4];
    float4 hv = ((const float4*)h)[i];
    float4 o;
    {
        float r = sigmoidf_(ir.x + hr.x), z = sigmoidf_(iz.x + hz.x);
        float nn = tanhf(in_.x + r * hn.x); o.x = (1.f - z) * nn + z * hv.x;
    }
    {
        float r = sigmoidf_(ir.y + hr.y), z = sigmoidf_(iz.y + hz.y);
        float nn = tanhf(in_.y + r * hn.y); o.y = (1.f - z) * nn + z * hv.y;
    }
    {
        float r = sigmoidf_(ir.z + hr.z), z = sigmoidf_(iz.z + hz.z);
        float nn = tanhf(in_.z + r * hn.z); o.z = (1.f - z) * nn + z * hv.z;
    }
    {
        float r = sigmoidf_(ir.w + hr.w), z = sigmoidf_(iz.w + hz.w);
        float nn = tanhf(in_.w + r * hn.w); o.w = (1.f - z) * nn + z * hv.w;
    }
    ((float4*)hnew)[i] = o;
}

// ---------------- gate score ----------------
__global__ void gate_kernel(const float* __restrict__ h, const float* __restrict__ gw,
                            const float* __restrict__ gb) {
    int w = (blockIdx.x * blockDim.x + threadIdx.x) >> 5;
    int lane = threadIdx.x & 31;
    if (w >= NN) return;
    float s = 0.f;
    const float* hr = h + (size_t)w * DD;
#pragma unroll
    for (int d = lane; d < DD; d += 32) s += hr[d] * gw[d];
#pragma unroll
    for (int o = 16; o; o >>= 1) s += __shfl_xor_sync(0xffffffffu, s, o);
    if (lane == 0) g_gate[w] = s + gb[0];
}

// ---------------- segment softmax + weighted pool -------------------------
__device__ __forceinline__ int lb_(const int* a, int n, int v) {
    int lo = 0, hi = n;
    while (lo < hi) { int m = (lo + hi) >> 1; if (a[m] < v) lo = m + 1; else hi = m; }
    return lo;
}

__global__ void pool_kernel(const float* __restrict__ h, const int* __restrict__ seg,
                            float* __restrict__ out) {
    __shared__ float red[256];
    __shared__ float s_scalar;
    int g = blockIdx.x, tid = threadIdx.x;
    int s = lb_(seg, NN, g), e = lb_(seg, NN, g + 1);

    float m = -INFINITY;
    for (int i = s + tid; i < e; i += 256) m = fmaxf(m, g_gate[i]);
    red[tid] = m; __syncthreads();
    for (int o = 128; o; o >>= 1) { if (tid < o) red[tid] = fmaxf(red[tid], red[tid + o]); __syncthreads(); }
    if (tid == 0) s_scalar = red[0];
    __syncthreads();
    float gm = s_scalar;
    __syncthreads();

    float sum = 0.f;
    for (int i = s + tid; i < e; i += 256) sum += expf(g_gate[i] - gm);
    red[tid] = sum; __syncthreads();
    for (int o = 128; o; o >>= 1) { if (tid < o) red[tid] += red[tid + o]; __syncthreads(); }
    if (tid == 0) s_scalar = red[0];
    __syncthreads();
    float denom = s_scalar;
    __syncthreads();

    float acc = 0.f;
    for (int i0 = s; i0 < e; i0 += 256) {
        int i = i0 + tid;
        red[tid] = (i < e) ? expf(g_gate[i] - gm) : 0.f;
        __syncthreads();
        int lim = min(256, e - i0);
        for (int k = 0; k < lim; k++) acc += h[(size_t)(i0 + k) * DD + tid] * red[k];
        __syncthreads();
    }
    out[g * DD + tid] = (e > s) ? acc / denom : 0.f;
}

// ---------------- launch ----------------
extern "C" void kernel_launch(void* const* d_in, const int* in_sizes, int n_in,
                              void* d_out, int out_size) {
    const int* x   = (const int*)d_in[0];
    const int* src = (const int*)d_in[1];
    const int* dst = (const int*)d_in[2];
    const int* et  = (const int*)d_in[3];
    const int* seg = (const int*)d_in[4];
    int base = (in_sizes[5] == 1) ? 6 : 5;
    const float* emb    = (const float*)d_in[base + 0];
    const float* Wmsg   = (const float*)d_in[base + 1];
    const float* bmsg   = (const float*)d_in[base + 2];
    const float* w_ih   = (const float*)d_in[base + 3];
    const float* w_hh   = (const float*)d_in[base + 4];
    const float* b_ih   = (const float*)d_in[base + 5];
    const float* b_hh   = (const float*)d_in[base + 6];
    const float* gate_w = (const float*)d_in[base + 7];
    const float* gate_b = (const float*)d_in[base + 8];
    float* out = (float*)d_out;

    float *ph0, *ph1, *pa, *pgi, *pgh;
    cudaGetSymbolAddress((void**)&ph0, g_h0);
    cudaGetSymbolAddress((void**)&ph1, g_h1);
    cudaGetSymbolAddress((void**)&pa,  g_a);
    cudaGetSymbolAddress((void**)&pgi, g_gi);
    cudaGetSymbolAddress((void**)&pgh, g_gh);

    const int elem4 = NN * DD / 4;
    embed_kernel<<<(elem4 + 255) / 256, 256>>>(x, emb, ph0);

    const int rowblk = (NN + BM - 1) / BM;         // 391
    float* hin = ph0;
    float* hout = ph1;
    for (int step = 0; step < NSTEPS; step++) {
        zero_kernel<<<(NET * NN * DD / 4 + 255) / 256, 256>>>();
        edge_scatter<<<(NE * 32 + 255) / 256, 256>>>(src, dst, et, hin);
        gemm_msg_tc<<<dim3(rowblk, DD / BN), 256>>>(Wmsg, bmsg);
        gemm_bt_tc<<<dim3(rowblk, G3 / BN), 256>>>(pa,  w_ih, b_ih, pgi, G3);
        gemm_bt_tc<<<dim3(rowblk, G3 / BN), 256>>>(hin, w_hh, b_hh, pgh, G3);
        gru_gate<<<(elem4 + 255) / 256, 256>>>(pgi, pgh, hin, hout);
        float* t = hin; hin = hout; hout = t;
    }
    gate_kernel<<<(NN * 32 + 255) / 256, 256>>>(hin, gate_w, gate_b);
    pool_kernel<<<NGR, 256>>>(hin, seg, out);
}

// round 3
// speedup vs baseline: 1.2783x; 1.2783x over previous
#include <cuda_runtime.h>
#include <math.h>
#include <stdint.h>

#define NN  50000
#define NE  800000
#define DD  256
#define NET 3
#define NSTEPS 5
#define NGR 64
#define G3  768   // 3*D

typedef uint32_t u32;

// ---------------- device scratch (no allocation allowed) ----------------
__device__ float g_h0[NN * DD];
__device__ float g_h1[NN * DD];
__device__ float g_acc[NET * NN * DD];      // fp32 atomic accumulation
__device__ int   g_cnt[NET][NN];
__device__ float g_gi[NN * G3];
__device__ float g_gh[NN * G3];
__device__ float g_gate[NN];

// split (tf32 hi/lo) operand arrays
__device__ u32 g_acch[NET][NN * DD];
__device__ u32 g_accl[NET][NN * DD];
__device__ u32 g_ah[NN * DD];
__device__ u32 g_al[NN * DD];
__device__ u32 g_hsh[2][NN * DD];
__device__ u32 g_hsl[2][NN * DD];
__device__ u32 g_wth[NET * DD * DD];        // W_msg transposed [e][n][k], split hi
__device__ u32 g_wtl[NET * DD * DD];
__device__ u32 g_wihh[G3 * DD];
__device__ u32 g_wihl[G3 * DD];
__device__ u32 g_whhh[G3 * DD];
__device__ u32 g_whhl[G3 * DD];

// ---------------- helpers ----------------
__device__ __forceinline__ void red4(float* p, float4 v) {
    asm volatile("red.global.add.v4.f32 [%0], {%1,%2,%3,%4};"
                 :: "l"(p), "f"(v.x), "f"(v.y), "f"(v.z), "f"(v.w) : "memory");
}

__device__ __forceinline__ float sigmoidf_(float x) { return 1.0f / (1.0f + expf(-x)); }

__device__ __forceinline__ void f32_split(float x, u32& hi, u32& lo) {
    u32 h;
    asm("cvt.rna.tf32.f32 %0, %1;" : "=r"(h) : "f"(x));
    float r = x - __uint_as_float(h);
    u32 l;
    asm("cvt.rna.tf32.f32 %0, %1;" : "=r"(l) : "f"(r));
    hi = h; lo = l;
}

__device__ __forceinline__ void mma_tf32(float c[4], const u32 a[4], u32 b0, u32 b1) {
    asm volatile("mma.sync.aligned.m16n8k8.row.col.f32.tf32.tf32.f32 "
                 "{%0,%1,%2,%3}, {%4,%5,%6,%7}, {%8,%9}, {%0,%1,%2,%3};"
                 : "+f"(c[0]), "+f"(c[1]), "+f"(c[2]), "+f"(c[3])
                 : "r"(a[0]), "r"(a[1]), "r"(a[2]), "r"(a[3]), "r"(b0), "r"(b1));
}

__device__ __forceinline__ u32 sptr(const void* p) {
    return (u32)__cvta_generic_to_shared(p);
}
__device__ __forceinline__ void cpa16(u32 dst, const void* src, int sz) {
    asm volatile("cp.async.cg.shared.global [%0], [%1], 16, %2;" :: "r"(dst), "l"(src), "r"(sz));
}
__device__ __forceinline__ void cp_commit() { asm volatile("cp.async.commit_group;"); }
__device__ __forceinline__ void cp_wait1()  { asm volatile("cp.async.wait_group 1;"); }

// ---------------- weight split (once per launch) ----------------
__global__ void split_weights(const float* __restrict__ Wmsg, const float* __restrict__ wih,
                              const float* __restrict__ whh) {
    int i = blockIdx.x * blockDim.x + threadIdx.x;
    if (i < NET * DD * DD) {
        // out [e][n][k] = in [e][k][n]
        int e = i >> 16, r = i & 65535, n = r >> 8, k = r & 255;
        u32 h, l;
        f32_split(Wmsg[(e << 16) + (k << 8) + n], h, l);
        g_wth[i] = h; g_wtl[i] = l;
    }
    if (i < G3 * DD) {
        u32 h, l;
        f32_split(wih[i], h, l); g_wihh[i] = h; g_wihl[i] = l;
        f32_split(whh[i], h, l); g_whhh[i] = h; g_whhl[i] = l;
    }
}

// ---------------- init: h = emb[x] (fp32 + split) ----------------
__global__ void embed_kernel(const int* __restrict__ x, const float* __restrict__ emb,
                             float* __restrict__ h, u32* __restrict__ hh, u32* __restrict__ hl) {
    int i = blockIdx.x * blockDim.x + threadIdx.x;
    const int nf4 = DD / 4;
    if (i >= NN * nf4) return;
    int n = i / nf4, d4 = i - n * nf4;
    int row = x[n];
    float4 v = ((const float4*)(emb + (size_t)row * DD))[d4];
    ((float4*)h)[i] = v;
    uint4 H, L;
    f32_split(v.x, H.x, L.x); f32_split(v.y, H.y, L.y);
    f32_split(v.z, H.z, L.z); f32_split(v.w, H.w, L.w);
    ((uint4*)hh)[i] = H; ((uint4*)hl)[i] = L;
}

// ---------------- zero acc + cnt ----------------
__global__ void zero_kernel() {
    int i = blockIdx.x * blockDim.x + threadIdx.x;
    const int TOT4 = NET * NN * DD / 4;
    if (i < TOT4) ((float4*)g_acc)[i] = make_float4(0.f, 0.f, 0.f, 0.f);
    if (i < NET * NN) ((int*)g_cnt)[i] = 0;
}

// ---------------- edge scatter (fp32 atomics) ----------------
__global__ void edge_scatter(const int* __restrict__ src, const int* __restrict__ dst,
                             const int* __restrict__ et, const float* __restrict__ h) {
    int w = (blockIdx.x * blockDim.x + threadIdx.x) >> 5;
    int lane = threadIdx.x & 31;
    if (w >= NE) return;
    int s = __ldg(src + w), d = __ldg(dst + w), t = __ldg(et + w);
    const float4* hs = (const float4*)(h + (size_t)s * DD);
    float* out = g_acc + ((size_t)t * NN + d) * DD;
#pragma unroll
    for (int i = 0; i < 2; i++) {
        int c = lane + 32 * i;
        float4 v = hs[c];
        red4(out + 4 * c, v);
    }
    if (lane == 0) atomicAdd(&g_cnt[t][d], 1);
}

// ---------------- split acc fp32 -> tf32 hi/lo ----------------
__global__ void split_acc() {
    int i = blockIdx.x * blockDim.x + threadIdx.x;
    const int TOT4 = NET * NN * DD / 4;
    if (i >= TOT4) return;
    float4 v = ((const float4*)g_acc)[i];
    uint4 H, L;
    f32_split(v.x, H.x, L.x); f32_split(v.y, H.y, L.y);
    f32_split(v.z, H.z, L.z); f32_split(v.w, H.w, L.w);
    ((uint4*)g_acch)[i] = H; ((uint4*)g_accl)[i] = L;
}

// ---------------- TC GEMM core: 128x128 tile, cp.async double buffer ------
#define BM 128
#define BN 128
#define KS 20                 // smem row stride (16 k + 4 pad) -> conflict-free
#define MATS (128 * KS)       // 2560 u32 per matrix per stage
#define STGS (4 * MATS)       // Ah, Al, Bh, Bl
#define SMEM_BYTES (2 * STGS * 4)

// load one stage: A rows [row0,row0+128) x k[kc,kc+16), B rows [bcol0,+128) same k
__device__ __forceinline__ void load_stage(u32* Sb,
                                           const u32* __restrict__ Agh, const u32* __restrict__ Agl,
                                           const u32* __restrict__ Bgh, const u32* __restrict__ Bgl,
                                           int row0, int rowmax, int bcol0, int kc, int tid) {
    u32 sA = sptr(Sb);
    u32 sAl = sA + MATS * 4, sBh = sA + 2 * MATS * 4, sBl = sA + 3 * MATS * 4;
#pragma unroll
    for (int q2 = 0; q2 < 2; q2++) {
        int q = tid + q2 * 256;
        int m = q >> 2, sg = (q & 3) << 2;
        int row = row0 + m;
        int sz = (row < rowmax) ? 16 : 0;
        int ra = (row < rowmax) ? row : 0;
        size_t go = (size_t)ra * DD + kc + sg;
        u32 so = (u32)(m * KS + sg) * 4;
        cpa16(sA + so, Agh + go, sz);
        cpa16(sAl + so, Agl + go, sz);
        size_t gb = (size_t)(bcol0 + m) * DD + kc + sg;
        cpa16(sBh + so, Bgh + gb, 16);
        cpa16(sBl + so, Bgl + gb, 16);
    }
}

__device__ __forceinline__ void mma_stage(float acc[4][4][4], const u32* Sb,
                                          int warp_m, int warp_n, int lane) {
    const u32* Ah = Sb;
    const u32* Al = Sb + MATS;
    const u32* Bh = Sb + 2 * MATS;
    const u32* Bl = Sb + 3 * MATS;
    int g = lane >> 2, kq = lane & 3;
#pragma unroll
    for (int kg = 0; kg < 16; kg += 8) {
        u32 ah[4][4], al[4][4];
#pragma unroll
        for (int i = 0; i < 4; i++) {
            int m = warp_m * 64 + i * 16 + g;
            int b0 = m * KS + kg + kq, b8 = (m + 8) * KS + kg + kq;
            ah[i][0] = Ah[b0]; ah[i][1] = Ah[b8]; ah[i][2] = Ah[b0 + 4]; ah[i][3] = Ah[b8 + 4];
            al[i][0] = Al[b0]; al[i][1] = Al[b8]; al[i][2] = Al[b0 + 4]; al[i][3] = Al[b8 + 4];
        }
#pragma unroll
        for (int j = 0; j < 4; j++) {
            int n = warp_n * 32 + j * 8 + g;
            int nb = n * KS + kg + kq;
            u32 bh0 = Bh[nb], bh1 = Bh[nb + 4];
            u32 bl0 = Bl[nb], bl1 = Bl[nb + 4];
#pragma unroll
            for (int i = 0; i < 4; i++) {
                mma_tf32(acc[i][j], ah[i], bh0, bh1);
                mma_tf32(acc[i][j], al[i], bh0, bh1);
                mma_tf32(acc[i][j], ah[i], bl0, bl1);
            }
        }
    }
}

// a = sum_et acc_et @ W_et + sum_et cnt_et*b_et ; writes SPLIT a (g_ah/g_al)
__global__ void __launch_bounds__(256)
gemm_msg_tc(const float* __restrict__ bmsg) {
    extern __shared__ u32 S[];
    int tid = threadIdx.x, lane = tid & 31, wid = tid >> 5;
    int warp_m = wid & 1, warp_n = wid >> 1;
    int row0 = blockIdx.x * BM, col0 = blockIdx.y * BN;
    float acc[4][4][4];
#pragma unroll
    for (int i = 0; i < 4; i++)
#pragma unroll
        for (int j = 0; j < 4; j++)
#pragma unroll
            for (int q = 0; q < 4; q++) acc[i][j][q] = 0.f;

    const int NKC = NET * 16;
    load_stage(S, g_acch[0], g_accl[0], g_wth, g_wtl, row0, NN, col0, 0, tid);
    cp_commit();
    for (int c = 0; c < NKC; c++) {
        int nc = c + 1;
        if (nc < NKC) {
            int e = nc >> 4, kc = (nc & 15) << 4;
            load_stage(S + (nc & 1) * STGS, g_acch[e], g_accl[e],
                       g_wth + (size_t)e * DD * DD, g_wtl + (size_t)e * DD * DD,
                       row0, NN, col0, kc, tid);
        }
        cp_commit();
        cp_wait1();
        __syncthreads();
        mma_stage(acc, S + (c & 1) * STGS, warp_m, warp_n, lane);
        __syncthreads();
    }

    int g = lane >> 2, kq = lane & 3;
#pragma unroll
    for (int i = 0; i < 4; i++) {
#pragma unroll
        for (int rr = 0; rr < 2; rr++) {
            int r = row0 + warp_m * 64 + i * 16 + g + rr * 8;
            if (r >= NN) continue;
            float c0 = (float)g_cnt[0][r], c1 = (float)g_cnt[1][r], c2 = (float)g_cnt[2][r];
#pragma unroll
            for (int j = 0; j < 4; j++) {
                int n = col0 + warp_n * 32 + j * 8 + 2 * kq;
                float2 b0 = *(const float2*)(bmsg + 0 * DD + n);
                float2 b1 = *(const float2*)(bmsg + 1 * DD + n);
                float2 b2 = *(const float2*)(bmsg + 2 * DD + n);
                float ox = acc[i][j][rr * 2 + 0] + c0 * b0.x + c1 * b1.x + c2 * b2.x;
                float oy = acc[i][j][rr * 2 + 1] + c0 * b0.y + c1 * b1.y + c2 * b2.y;
                u32 xh, xl, yh, yl;
                f32_split(ox, xh, xl); f32_split(oy, yh, yl);
                size_t idx = (size_t)r * DD + n;
                *(uint2*)(g_ah + idx) = make_uint2(xh, yh);
                *(uint2*)(g_al + idx) = make_uint2(xl, yl);
            }
        }
    }
}

// C[n,j] = A@Bt^T + bias, A split [NN][256], Bt split [ncols][256], C fp32
__global__ void __launch_bounds__(256)
gemm_bt_tc(const u32* __restrict__ Agh, const u32* __restrict__ Agl,
           const u32* __restrict__ Bgh, const u32* __restrict__ Bgl,
           const float* __restrict__ bias, float* __restrict__ C, int ncols) {
    extern __shared__ u32 S[];
    int tid = threadIdx.x, lane = tid & 31, wid = tid >> 5;
    int warp_m = wid & 1, warp_n = wid >> 1;
    int row0 = blockIdx.x * BM, col0 = blockIdx.y * BN;
    float acc[4][4][4];
#pragma unroll
    for (int i = 0; i < 4; i++)
#pragma unroll
        for (int j = 0; j < 4; j++)
#pragma unroll
            for (int q = 0; q < 4; q++) acc[i][j][q] = 0.f;

    const int NKC = 16;
    load_stage(S, Agh, Agl, Bgh, Bgl, row0, NN, col0, 0, tid);
    cp_commit();
    for (int c = 0; c < NKC; c++) {
        int nc = c + 1;
        if (nc < NKC)
            load_stage(S + (nc & 1) * STGS, Agh, Agl, Bgh, Bgl, row0, NN, col0, nc << 4, tid);
        cp_commit();
        cp_wait1();
        __syncthreads();
        mma_stage(acc, S + (c & 1) * STGS, warp_m, warp_n, lane);
        __syncthreads();
    }

    int g = lane >> 2, kq = lane & 3;
#pragma unroll
    for (int j = 0; j < 4; j++) {
        int n = col0 + warp_n * 32 + j * 8 + 2 * kq;
        float2 bv = *(const float2*)(bias + n);
#pragma unroll
        for (int i = 0; i < 4; i++) {
            int r = row0 + warp_m * 64 + i * 16 + g;
            if (r < NN) {
                float2 o = {acc[i][j][0] + bv.x, acc[i][j][1] + bv.y};
                *(float2*)(C + (size_t)r * ncols + n) = o;
            }
            if (r + 8 < NN) {
                float2 o = {acc[i][j][2] + bv.x, acc[i][j][3] + bv.y};
                *(float2*)(C + (size_t)(r + 8) * ncols + n) = o;
            }
        }
    }
}

// ---------------- GRU gates (elementwise, fp32 + split h out) -------------
__global__ void gru_gate(const float* __restrict__ gi, const float* __restrict__ gh,
                         const float* __restrict__ h, float* __restrict__ hnew,
                         u32* __restrict__ hnh, u32* __restrict__ hnl) {
    int i = blockIdx.x * blockDim.x + threadIdx.x;
    const int nf4 = DD / 4;
    if (i >= NN * nf4) return;
    int n = i / nf4, d4 = i - n * nf4;
    const float4* GI4 = (const float4*)(gi + (size_t)n * G3);
    const float4* GH4 = (const float4*)(gh + (size_t)n * G3);
    float4 ir = GI4[d4], iz = GI4[64 + d4], in_ = GI4[128 + d4];
    float4 hr = GH4[d4], hz = GH4[64 + d4], hn = GH4[128 + d4];
    float4 hv = ((const float4*)h)[i];
    float4 o;
    {
        float r = sigmoidf_(ir.x + hr.x), z = sigmoidf_(iz.x + hz.x);
        float nn = tanhf(in_.x + r * hn.x); o.x = (1.f - z) * nn + z * hv.x;
    }
    {
        float r = sigmoidf_(ir.y + hr.y), z = sigmoidf_(iz.y + hz.y);
        float nn = tanhf(in_.y + r * hn.y); o.y = (1.f - z) * nn + z * hv.y;
    }
    {
        float r = sigmoidf_(ir.z + hr.z), z = sigmoidf_(iz.z + hz.z);
        float nn = tanhf(in_.z + r * hn.z); o.z = (1.f - z) * nn + z * hv.z;
    }
    {
        float r = sigmoidf_(ir.w + hr.w), z = sigmoidf_(iz.w + hz.w);
        float nn = tanhf(in_.w + r * hn.w); o.w = (1.f - z) * nn + z * hv.w;
    }
    ((float4*)hnew)[i] = o;
    uint4 H, L;
    f32_split(o.x, H.x, L.x); f32_split(o.y, H.y, L.y);
    f32_split(o.z, H.z, L.z); f32_split(o.w, H.w, L.w);
    ((uint4*)hnh)[i] = H; ((uint4*)hnl)[i] = L;
}

// ---------------- gate score ----------------
__global__ void gate_kernel(const float* __restrict__ h, const float* __restrict__ gw,
                            const float* __restrict__ gb) {
    int w = (blockIdx.x * blockDim.x + threadIdx.x) >> 5;
    int lane = threadIdx.x & 31;
    if (w >= NN) return;
    float s = 0.f;
    const float* hr = h + (size_t)w * DD;
#pragma unroll
    for (int d = lane; d < DD; d += 32) s += hr[d] * gw[d];
#pragma unroll
    for (int o = 16; o; o >>= 1) s += __shfl_xor_sync(0xffffffffu, s, o);
    if (lane == 0) g_gate[w] = s + gb[0];
}

// ---------------- segment softmax + weighted pool -------------------------
__device__ __forceinline__ int lb_(const int* a, int n, int v) {
    int lo = 0, hi = n;
    while (lo < hi) { int m = (lo + hi) >> 1; if (a[m] < v) lo = m + 1; else hi = m; }
    return lo;
}

__global__ void pool_kernel(const float* __restrict__ h, const int* __restrict__ seg,
                            float* __restrict__ out) {
    __shared__ float red[256];
    __shared__ float s_scalar;
    int g = blockIdx.x, tid = threadIdx.x;
    int s = lb_(seg, NN, g), e = lb_(seg, NN, g + 1);

    float m = -INFINITY;
    for (int i = s + tid; i < e; i += 256) m = fmaxf(m, g_gate[i]);
    red[tid] = m; __syncthreads();
    for (int o = 128; o; o >>= 1) { if (tid < o) red[tid] = fmaxf(red[tid], red[tid + o]); __syncthreads(); }
    if (tid == 0) s_scalar = red[0];
    __syncthreads();
    float gm = s_scalar;
    __syncthreads();

    float sum = 0.f;
    for (int i = s + tid; i < e; i += 256) sum += expf(g_gate[i] - gm);
    red[tid] = sum; __syncthreads();
    for (int o = 128; o; o >>= 1) { if (tid < o) red[tid] += red[tid + o]; __syncthreads(); }
    if (tid == 0) s_scalar = red[0];
    __syncthreads();
    float denom = s_scalar;
    __syncthreads();

    float acc = 0.f;
    for (int i0 = s; i0 < e; i0 += 256) {
        int i = i0 + tid;
        red[tid] = (i < e) ? expf(g_gate[i] - gm) : 0.f;
        __syncthreads();
        int lim = min(256, e - i0);
        for (int k = 0; k < lim; k++) acc += h[(size_t)(i0 + k) * DD + tid] * red[k];
        __syncthreads();
    }
    out[g * DD + tid] = (e > s) ? acc / denom : 0.f;
}

// ---------------- launch ----------------
extern "C" void kernel_launch(void* const* d_in, const int* in_sizes, int n_in,
                              void* d_out, int out_size) {
    const int* x   = (const int*)d_in[0];
    const int* src = (const int*)d_in[1];
    const int* dst = (const int*)d_in[2];
    const int* et  = (const int*)d_in[3];
    const int* seg = (const int*)d_in[4];
    int base = (in_sizes[5] == 1) ? 6 : 5;
    const float* emb    = (const float*)d_in[base + 0];
    const float* Wmsg   = (const float*)d_in[base + 1];
    const float* bmsg   = (const float*)d_in[base + 2];
    const float* w_ih   = (const float*)d_in[base + 3];
    const float* w_hh   = (const float*)d_in[base + 4];
    const float* b_ih   = (const float*)d_in[base + 5];
    const float* b_hh   = (const float*)d_in[base + 6];
    const float* gate_w = (const float*)d_in[base + 7];
    const float* gate_b = (const float*)d_in[base + 8];
    float* out = (float*)d_out;

    static int smem_set = 0;
    if (!smem_set) {
        cudaFuncSetAttribute(gemm_msg_tc, cudaFuncAttributeMaxDynamicSharedMemorySize, SMEM_BYTES);
        cudaFuncSetAttribute(gemm_bt_tc,  cudaFuncAttributeMaxDynamicSharedMemorySize, SMEM_BYTES);
        smem_set = 1;
    }

    float *ph0, *ph1, *pgi, *pgh;
    u32 *pah, *pal, *phh, *phl, *pwihh, *pwihl, *pwhhh, *pwhhl;
    cudaGetSymbolAddress((void**)&ph0, g_h0);
    cudaGetSymbolAddress((void**)&ph1, g_h1);
    cudaGetSymbolAddress((void**)&pgi, g_gi);
    cudaGetSymbolAddress((void**)&pgh, g_gh);
    cudaGetSymbolAddress((void**)&pah, g_ah);
    cudaGetSymbolAddress((void**)&pal, g_al);
    cudaGetSymbolAddress((void**)&phh, g_hsh);
    cudaGetSymbolAddress((void**)&phl, g_hsl);
    cudaGetSymbolAddress((void**)&pwihh, g_wihh);
    cudaGetSymbolAddress((void**)&pwihl, g_wihl);
    cudaGetSymbolAddress((void**)&pwhhh, g_whhh);
    cudaGetSymbolAddress((void**)&pwhhl, g_whhl);

    split_weights<<<(NET * DD * DD + 255) / 256, 256>>>(Wmsg, w_ih, w_hh);

    const int elem4 = NN * DD / 4;
    embed_kernel<<<(elem4 + 255) / 256, 256>>>(x, emb, ph0, phh, phl);

    const int rowblk = (NN + BM - 1) / BM;   // 391
    float* hin = ph0;
    float* hout = ph1;
    int side = 0;
    for (int step = 0; step < NSTEPS; step++) {
        u32* hinh = phh + (size_t)side * NN * DD;
        u32* hinl = phl + (size_t)side * NN * DD;
        u32* houth = phh + (size_t)(1 - side) * NN * DD;
        u32* houtl = phl + (size_t)(1 - side) * NN * DD;

        zero_kernel<<<(NET * NN * DD / 4 + 255) / 256, 256>>>();
        edge_scatter<<<(NE * 32 + 255) / 256, 256>>>(src, dst, et, hin);
        split_acc<<<(NET * NN * DD / 4 + 255) / 256, 256>>>();
        gemm_msg_tc<<<dim3(rowblk, DD / BN), 256, SMEM_BYTES>>>(bmsg);
        gemm_bt_tc<<<dim3(rowblk, G3 / BN), 256, SMEM_BYTES>>>(pah, pal, pwihh, pwihl, b_ih, pgi, G3);
        gemm_bt_tc<<<dim3(rowblk, G3 / BN), 256, SMEM_BYTES>>>(hinh, hinl, pwhhh, pwhhl, b_hh, pgh, G3);
        gru_gate<<<(elem4 + 255) / 256, 256>>>(pgi, pgh, hin, hout, houth, houtl);

        float* t = hin; hin = hout; hout = t;
        side = 1 - side;
    }
    gate_kernel<<<(NN * 32 + 255) / 256, 256>>>(hin, gate_w, gate_b);
    pool_kernel<<<NGR, 256>>>(hin, seg, out);
}

// round 4
// speedup vs baseline: 1.2933x; 1.0118x over previous
#include <cuda_runtime.h>
#include <math.h>
#include <stdint.h>

#define NN  50000
#define NE  800000
#define DD  256
#define NET 3
#define NSTEPS 5
#define NGR 64
#define G3  768   // 3*D
#define BINS (NET * NN)

typedef uint32_t u32;

// ---------------- device scratch (no allocation allowed) ----------------
__device__ float g_h0[NN * DD];
__device__ float g_h1[NN * DD];
__device__ int   g_cnt[BINS];
__device__ float g_gi[NN * G3];
__device__ float g_gh[NN * G3];
__device__ float g_gate[NN];

// CSR
__device__ int g_binoff[BINS + 1];
__device__ int g_cursor[BINS];
__device__ int g_bsum[256];
__device__ int g_bscan[256];
__device__ int g_esrc[NE];

// split (tf32 hi/lo) operand arrays
__device__ u32 g_acch[NET][NN * DD];
__device__ u32 g_accl[NET][NN * DD];
__device__ u32 g_ah[NN * DD];
__device__ u32 g_al[NN * DD];
__device__ u32 g_hsh[2][NN * DD];
__device__ u32 g_hsl[2][NN * DD];
__device__ u32 g_wth[NET * DD * DD];        // W_msg transposed [e][n][k], split hi
__device__ u32 g_wtl[NET * DD * DD];
__device__ u32 g_wihh[G3 * DD];
__device__ u32 g_wihl[G3 * DD];
__device__ u32 g_whhh[G3 * DD];
__device__ u32 g_whhl[G3 * DD];

// ---------------- helpers ----------------
__device__ __forceinline__ float sigmoidf_(float x) { return 1.0f / (1.0f + expf(-x)); }

__device__ __forceinline__ void f32_split(float x, u32& hi, u32& lo) {
    u32 h;
    asm("cvt.rna.tf32.f32 %0, %1;" : "=r"(h) : "f"(x));
    float r = x - __uint_as_float(h);
    u32 l;
    asm("cvt.rna.tf32.f32 %0, %1;" : "=r"(l) : "f"(r));
    hi = h; lo = l;
}

__device__ __forceinline__ void mma_tf32(float c[4], const u32 a[4], u32 b0, u32 b1) {
    asm volatile("mma.sync.aligned.m16n8k8.row.col.f32.tf32.tf32.f32 "
                 "{%0,%1,%2,%3}, {%4,%5,%6,%7}, {%8,%9}, {%0,%1,%2,%3};"
                 : "+f"(c[0]), "+f"(c[1]), "+f"(c[2]), "+f"(c[3])
                 : "r"(a[0]), "r"(a[1]), "r"(a[2]), "r"(a[3]), "r"(b0), "r"(b1));
}

__device__ __forceinline__ u32 sptr(const void* p) {
    return (u32)__cvta_generic_to_shared(p);
}
__device__ __forceinline__ void cpa16(u32 dst, const void* src, int sz) {
    asm volatile("cp.async.cg.shared.global [%0], [%1], 16, %2;" :: "r"(dst), "l"(src), "r"(sz));
}
__device__ __forceinline__ void cp_commit() { asm volatile("cp.async.commit_group;"); }
__device__ __forceinline__ void cp_wait1()  { asm volatile("cp.async.wait_group 1;"); }

// ================= CSR build (once per launch) =================
__global__ void zero_cursor() {
    int i = blockIdx.x * blockDim.x + threadIdx.x;
    if (i < BINS) g_cursor[i] = 0;
}

__global__ void hist_kernel(const int* __restrict__ dst, const int* __restrict__ et) {
    int e = blockIdx.x * blockDim.x + threadIdx.x;
    if (e >= NE) return;
    atomicAdd(&g_cursor[et[e] * NN + dst[e]], 1);
}

// block sums over 1024-bin chunks
__global__ void scanA() {
    __shared__ int sh[256];
    int b = blockIdx.x, tid = threadIdx.x;
    int base = b * 1024 + tid * 4;
    int s = 0;
#pragma unroll
    for (int j = 0; j < 4; j++) {
        int idx = base + j;
        if (idx < BINS) s += g_cursor[idx];
    }
    sh[tid] = s; __syncthreads();
    for (int o = 128; o; o >>= 1) { if (tid < o) sh[tid] += sh[tid + o]; __syncthreads(); }
    if (tid == 0) g_bsum[b] = sh[0];
}

// single-block exclusive scan of block sums
__global__ void scanB(int nb) {
    __shared__ int sh[256];
    int tid = threadIdx.x;
    int v = (tid < nb) ? g_bsum[tid] : 0;
    sh[tid] = v; __syncthreads();
    for (int off = 1; off < 256; off <<= 1) {
        int t = (tid >= off) ? sh[tid - off] : 0;
        __syncthreads();
        sh[tid] += t;
        __syncthreads();
    }
    if (tid < nb) g_bscan[tid] = sh[tid] - v;
    if (tid == 0) g_binoff[BINS] = NE;
}

// per-chunk exclusive scan + global offset -> binoff, cursor
__global__ void scanC() {
    __shared__ int sh[256];
    int b = blockIdx.x, tid = threadIdx.x;
    int base = b * 1024 + tid * 4;
    int v[4];
    int s = 0;
#pragma unroll
    for (int j = 0; j < 4; j++) {
        int idx = base + j;
        v[j] = (idx < BINS) ? g_cursor[idx] : 0;
        s += v[j];
    }
    sh[tid] = s; __syncthreads();
    for (int off = 1; off < 256; off <<= 1) {
        int t = (tid >= off) ? sh[tid - off] : 0;
        __syncthreads();
        sh[tid] += t;
        __syncthreads();
    }
    int run = g_bscan[b] + (sh[tid] - s);
#pragma unroll
    for (int j = 0; j < 4; j++) {
        int idx = base + j;
        if (idx < BINS) { g_binoff[idx] = run; g_cursor[idx] = run; run += v[j]; }
    }
}

__global__ void fill_kernel(const int* __restrict__ src, const int* __restrict__ dst,
                            const int* __restrict__ et) {
    int e = blockIdx.x * blockDim.x + threadIdx.x;
    if (e >= NE) return;
    int bin = et[e] * NN + dst[e];
    int pos = atomicAdd(&g_cursor[bin], 1);
    g_esrc[pos] = src[e];
}

// ================= per-step aggregation: warp per bin =================
__global__ void aggregate_kernel(const float* __restrict__ h) {
    int bin = blockIdx.x * 8 + (threadIdx.x >> 5);
    int lane = threadIdx.x & 31;
    if (bin >= BINS) return;
    int o0 = g_binoff[bin], o1 = g_binoff[bin + 1];
    float4 a0 = make_float4(0.f, 0.f, 0.f, 0.f);
    float4 a1 = make_float4(0.f, 0.f, 0.f, 0.f);
    for (int e = o0; e < o1; e++) {
        int s = __ldg(g_esrc + e);
        const float4* hp = (const float4*)(h + (size_t)s * DD);
        float4 v0 = __ldg(hp + lane);
        float4 v1 = __ldg(hp + lane + 32);
        a0.x += v0.x; a0.y += v0.y; a0.z += v0.z; a0.w += v0.w;
        a1.x += v1.x; a1.y += v1.y; a1.z += v1.z; a1.w += v1.w;
    }
    u32* ach = (u32*)g_acch;
    u32* acl = (u32*)g_accl;
    size_t base = (size_t)bin * DD;
    uint4 H, L;
    f32_split(a0.x, H.x, L.x); f32_split(a0.y, H.y, L.y);
    f32_split(a0.z, H.z, L.z); f32_split(a0.w, H.w, L.w);
    *(uint4*)(ach + base + lane * 4) = H;
    *(uint4*)(acl + base + lane * 4) = L;
    f32_split(a1.x, H.x, L.x); f32_split(a1.y, H.y, L.y);
    f32_split(a1.z, H.z, L.z); f32_split(a1.w, H.w, L.w);
    *(uint4*)(ach + base + (lane + 32) * 4) = H;
    *(uint4*)(acl + base + (lane + 32) * 4) = L;
    if (lane == 0) g_cnt[bin] = o1 - o0;
}

// ---------------- weight split (once per launch) ----------------
__global__ void split_weights(const float* __restrict__ Wmsg, const float* __restrict__ wih,
                              const float* __restrict__ whh) {
    int i = blockIdx.x * blockDim.x + threadIdx.x;
    if (i < NET * DD * DD) {
        int e = i >> 16, r = i & 65535, n = r >> 8, k = r & 255;
        u32 h, l;
        f32_split(Wmsg[(e << 16) + (k << 8) + n], h, l);
        g_wth[i] = h; g_wtl[i] = l;
    }
    if (i < G3 * DD) {
        u32 h, l;
        f32_split(wih[i], h, l); g_wihh[i] = h; g_wihl[i] = l;
        f32_split(whh[i], h, l); g_whhh[i] = h; g_whhl[i] = l;
    }
}

// ---------------- init: h = emb[x] (fp32 + split) ----------------
__global__ void embed_kernel(const int* __restrict__ x, const float* __restrict__ emb,
                             float* __restrict__ h, u32* __restrict__ hh, u32* __restrict__ hl) {
    int i = blockIdx.x * blockDim.x + threadIdx.x;
    const int nf4 = DD / 4;
    if (i >= NN * nf4) return;
    int n = i / nf4, d4 = i - n * nf4;
    int row = x[n];
    float4 v = ((const float4*)(emb + (size_t)row * DD))[d4];
    ((float4*)h)[i] = v;
    uint4 H, L;
    f32_split(v.x, H.x, L.x); f32_split(v.y, H.y, L.y);
    f32_split(v.z, H.z, L.z); f32_split(v.w, H.w, L.w);
    ((uint4*)hh)[i] = H; ((uint4*)hl)[i] = L;
}

// ---------------- TC GEMM core: 128x128 tile, 3-stage cp.async ------------
#define BM 128
#define BN 128
#define KS 20
#define MATS (128 * KS)
#define STGS (4 * MATS)
#define NSTAGE 3
#define SMEM_BYTES (NSTAGE * STGS * 4)

__device__ __forceinline__ void load_stage(u32* Sb,
                                           const u32* __restrict__ Agh, const u32* __restrict__ Agl,
                                           const u32* __restrict__ Bgh, const u32* __restrict__ Bgl,
                                           int row0, int rowmax, int bcol0, int kc, int tid) {
    u32 sA = sptr(Sb);
    u32 sAl = sA + MATS * 4, sBh = sA + 2 * MATS * 4, sBl = sA + 3 * MATS * 4;
#pragma unroll
    for (int q2 = 0; q2 < 2; q2++) {
        int q = tid + q2 * 256;
        int m = q >> 2, sg = (q & 3) << 2;
        int row = row0 + m;
        int sz = (row < rowmax) ? 16 : 0;
        int ra = (row < rowmax) ? row : 0;
        size_t go = (size_t)ra * DD + kc + sg;
        u32 so = (u32)(m * KS + sg) * 4;
        cpa16(sA + so, Agh + go, sz);
        cpa16(sAl + so, Agl + go, sz);
        size_t gb = (size_t)(bcol0 + m) * DD + kc + sg;
        cpa16(sBh + so, Bgh + gb, 16);
        cpa16(sBl + so, Bgl + gb, 16);
    }
}

__device__ __forceinline__ void mma_stage(float acc[4][4][4], const u32* Sb,
                                          int warp_m, int warp_n, int lane) {
    const u32* Ah = Sb;
    const u32* Al = Sb + MATS;
    const u32* Bh = Sb + 2 * MATS;
    const u32* Bl = Sb + 3 * MATS;
    int g = lane >> 2, kq = lane & 3;
#pragma unroll
    for (int kg = 0; kg < 16; kg += 8) {
        u32 ah[4][4], al[4][4];
#pragma unroll
        for (int i = 0; i < 4; i++) {
            int m = warp_m * 64 + i * 16 + g;
            int b0 = m * KS + kg + kq, b8 = (m + 8) * KS + kg + kq;
            ah[i][0] = Ah[b0]; ah[i][1] = Ah[b8]; ah[i][2] = Ah[b0 + 4]; ah[i][3] = Ah[b8 + 4];
            al[i][0] = Al[b0]; al[i][1] = Al[b8]; al[i][2] = Al[b0 + 4]; al[i][3] = Al[b8 + 4];
        }
#pragma unroll
        for (int j = 0; j < 4; j++) {
            int n = warp_n * 32 + j * 8 + g;
            int nb = n * KS + kg + kq;
            u32 bh0 = Bh[nb], bh1 = Bh[nb + 4];
            u32 bl0 = Bl[nb], bl1 = Bl[nb + 4];
#pragma unroll
            for (int i = 0; i < 4; i++) {
                mma_tf32(acc[i][j], ah[i], bh0, bh1);
                mma_tf32(acc[i][j], al[i], bh0, bh1);
                mma_tf32(acc[i][j], ah[i], bl0, bl1);
            }
        }
    }
}

// a = sum_et acc_et @ W_et + cnt*b ; writes SPLIT a (g_ah/g_al)
__global__ void __launch_bounds__(256)
gemm_msg_tc(const float* __restrict__ bmsg) {
    extern __shared__ u32 S[];
    int tid = threadIdx.x, lane = tid & 31, wid = tid >> 5;
    int warp_m = wid & 1, warp_n = wid >> 1;
    int row0 = blockIdx.x * BM, col0 = blockIdx.y * BN;
    float acc[4][4][4];
#pragma unroll
    for (int i = 0; i < 4; i++)
#pragma unroll
        for (int j = 0; j < 4; j++)
#pragma unroll
            for (int q = 0; q < 4; q++) acc[i][j][q] = 0.f;

    const int NKC = NET * 16;
#pragma unroll
    for (int s = 0; s < NSTAGE - 1; s++) {
        load_stage(S + s * STGS, g_acch[0], g_accl[0], g_wth, g_wtl, row0, NN, col0, s << 4, tid);
        cp_commit();
    }
    for (int c = 0; c < NKC; c++) {
        cp_wait1();
        __syncthreads();
        int nxt = c + NSTAGE - 1;
        if (nxt < NKC) {
            int e = nxt >> 4, kc = (nxt & 15) << 4;
            load_stage(S + (nxt % NSTAGE) * STGS, g_acch[e], g_accl[e],
                       g_wth + (size_t)e * DD * DD, g_wtl + (size_t)e * DD * DD,
                       row0, NN, col0, kc, tid);
        }
        cp_commit();
        mma_stage(acc, S + (c % NSTAGE) * STGS, warp_m, warp_n, lane);
    }

    int g = lane >> 2, kq = lane & 3;
#pragma unroll
    for (int i = 0; i < 4; i++) {
#pragma unroll
        for (int rr = 0; rr < 2; rr++) {
            int r = row0 + warp_m * 64 + i * 16 + g + rr * 8;
            if (r >= NN) continue;
            float c0 = (float)g_cnt[0 * NN + r], c1 = (float)g_cnt[1 * NN + r], c2 = (float)g_cnt[2 * NN + r];
#pragma unroll
            for (int j = 0; j < 4; j++) {
                int n = col0 + warp_n * 32 + j * 8 + 2 * kq;
                float2 b0 = *(const float2*)(bmsg + 0 * DD + n);
                float2 b1 = *(const float2*)(bmsg + 1 * DD + n);
                float2 b2 = *(const float2*)(bmsg + 2 * DD + n);
                float ox = acc[i][j][rr * 2 + 0] + c0 * b0.x + c1 * b1.x + c2 * b2.x;
                float oy = acc[i][j][rr * 2 + 1] + c0 * b0.y + c1 * b1.y + c2 * b2.y;
                u32 xh, xl, yh, yl;
                f32_split(ox, xh, xl); f32_split(oy, yh, yl);
                size_t idx = (size_t)r * DD + n;
                *(uint2*)(g_ah + idx) = make_uint2(xh, yh);
                *(uint2*)(g_al + idx) = make_uint2(xl, yl);
            }
        }
    }
}

// merged gi/gh: z=0 -> (A0,W0,b0)->C0, z=1 -> (A1,W1,b1)->C1; ncols=G3
__global__ void __launch_bounds__(256)
gemm_bt2_tc(const u32* __restrict__ A0h, const u32* __restrict__ A0l,
            const u32* __restrict__ W0h, const u32* __restrict__ W0l,
            const float* __restrict__ b0v, float* __restrict__ C0,
            const u32* __restrict__ A1h, const u32* __restrict__ A1l,
            const u32* __restrict__ W1h, const u32* __restrict__ W1l,
            const float* __restrict__ b1v, float* __restrict__ C1) {
    extern __shared__ u32 S[];
    int z = blockIdx.z;
    const u32* Agh = z ? A1h : A0h;
    const u32* Agl = z ? A1l : A0l;
    const u32* Bgh = z ? W1h : W0h;
    const u32* Bgl = z ? W1l : W0l;
    const float* bias = z ? b1v : b0v;
    float* C = z ? C1 : C0;

    int tid = threadIdx.x, lane = tid & 31, wid = tid >> 5;
    int warp_m = wid & 1, warp_n = wid >> 1;
    int row0 = blockIdx.x * BM, col0 = blockIdx.y * BN;
    float acc[4][4][4];
#pragma unroll
    for (int i = 0; i < 4; i++)
#pragma unroll
        for (int j = 0; j < 4; j++)
#pragma unroll
            for (int q = 0; q < 4; q++) acc[i][j][q] = 0.f;

    const int NKC = 16;
#pragma unroll
    for (int s = 0; s < NSTAGE - 1; s++) {
        load_stage(S + s * STGS, Agh, Agl, Bgh, Bgl, row0, NN, col0, s << 4, tid);
        cp_commit();
    }
    for (int c = 0; c < NKC; c++) {
        cp_wait1();
        __syncthreads();
        int nxt = c + NSTAGE - 1;
        if (nxt < NKC)
            load_stage(S + (nxt % NSTAGE) * STGS, Agh, Agl, Bgh, Bgl, row0, NN, col0, nxt << 4, tid);
        cp_commit();
        mma_stage(acc, S + (c % NSTAGE) * STGS, warp_m, warp_n, lane);
    }

    int g = lane >> 2, kq = lane & 3;
#pragma unroll
    for (int j = 0; j < 4; j++) {
        int n = col0 + warp_n * 32 + j * 8 + 2 * kq;
        float2 bv = *(const float2*)(bias + n);
#pragma unroll
        for (int i = 0; i < 4; i++) {
            int r = row0 + warp_m * 64 + i * 16 + g;
            if (r < NN) {
                float2 o = {acc[i][j][0] + bv.x, acc[i][j][1] + bv.y};
                *(float2*)(C + (size_t)r * G3 + n) = o;
            }
            if (r + 8 < NN) {
                float2 o = {acc[i][j][2] + bv.x, acc[i][j][3] + bv.y};
                *(float2*)(C + (size_t)(r + 8) * G3 + n) = o;
            }
        }
    }
}

// ---------------- GRU gates (elementwise, fp32 + split h out) -------------
__global__ void gru_gate(const float* __restrict__ gi, const float* __restrict__ gh,
                         const float* __restrict__ h, float* __restrict__ hnew,
                         u32* __restrict__ hnh, u32* __restrict__ hnl) {
    int i = blockIdx.x * blockDim.x + threadIdx.x;
    const int nf4 = DD / 4;
    if (i >= NN * nf4) return;
    int n = i / nf4, d4 = i - n * nf4;
    const float4* GI4 = (const float4*)(gi + (size_t)n * G3);
    const float4* GH4 = (const float4*)(gh + (size_t)n * G3);
    float4 ir = GI4[d4], iz = GI4[64 + d4], in_ = GI4[128 + d4];
    float4 hr = GH4[d4], hz = GH4[64 + d4], hn = GH4[128 + d4];
    float4 hv = ((const float4*)h)[i];
    float4 o;
    {
        float r = sigmoidf_(ir.x + hr.x), z = sigmoidf_(iz.x + hz.x);
        float nn = tanhf(in_.x + r * hn.x); o.x = (1.f - z) * nn + z * hv.x;
    }
    {
        float r = sigmoidf_(ir.y + hr.y), z = sigmoidf_(iz.y + hz.y);
        float nn = tanhf(in_.y + r * hn.y); o.y = (1.f - z) * nn + z * hv.y;
    }
    {
        float r = sigmoidf_(ir.z + hr.z), z = sigmoidf_(iz.z + hz.z);
        float nn = tanhf(in_.z + r * hn.z); o.z = (1.f - z) * nn + z * hv.z;
    }
    {
        float r = sigmoidf_(ir.w + hr.w), z = sigmoidf_(iz.w + hz.w);
        float nn = tanhf(in_.w + r * hn.w); o.w = (1.f - z) * nn + z * hv.w;
    }
    ((float4*)hnew)[i] = o;
    uint4 H, L;
    f32_split(o.x, H.x, L.x); f32_split(o.y, H.y, L.y);
    f32_split(o.z, H.z, L.z); f32_split(o.w, H.w, L.w);
    ((uint4*)hnh)[i] = H; ((uint4*)hnl)[i] = L;
}

// ---------------- gate score ----------------
__global__ void gate_kernel(const float* __restrict__ h, const float* __restrict__ gw,
                            const float* __restrict__ gb) {
    int w = (blockIdx.x * blockDim.x + threadIdx.x) >> 5;
    int lane = threadIdx.x & 31;
    if (w >= NN) return;
    float s = 0.f;
    const float* hr = h + (size_t)w * DD;
#pragma unroll
    for (int d = lane; d < DD; d += 32) s += hr[d] * gw[d];
#pragma unroll
    for (int o = 16; o; o >>= 1) s += __shfl_xor_sync(0xffffffffu, s, o);
    if (lane == 0) g_gate[w] = s + gb[0];
}

// ---------------- segment softmax + weighted pool -------------------------
__device__ __forceinline__ int lb_(const int* a, int n, int v) {
    int lo = 0, hi = n;
    while (lo < hi) { int m = (lo + hi) >> 1; if (a[m] < v) lo = m + 1; else hi = m; }
    return lo;
}

__global__ void pool_kernel(const float* __restrict__ h, const int* __restrict__ seg,
                            float* __restrict__ out) {
    __shared__ float red[256];
    __shared__ float s_scalar;
    int g = blockIdx.x, tid = threadIdx.x;
    int s = lb_(seg, NN, g), e = lb_(seg, NN, g + 1);

    float m = -INFINITY;
    for (int i = s + tid; i < e; i += 256) m = fmaxf(m, g_gate[i]);
    red[tid] = m; __syncthreads();
    for (int o = 128; o; o >>= 1) { if (tid < o) red[tid] = fmaxf(red[tid], red[tid + o]); __syncthreads(); }
    if (tid == 0) s_scalar = red[0];
    __syncthreads();
    float gm = s_scalar;
    __syncthreads();

    float sum = 0.f;
    for (int i = s + tid; i < e; i += 256) sum += expf(g_gate[i] - gm);
    red[tid] = sum; __syncthreads();
    for (int o = 128; o; o >>= 1) { if (tid < o) red[tid] += red[tid + o]; __syncthreads(); }
    if (tid == 0) s_scalar = red[0];
    __syncthreads();
    float denom = s_scalar;
    __syncthreads();

    float acc = 0.f;
    for (int i0 = s; i0 < e; i0 += 256) {
        int i = i0 + tid;
        red[tid] = (i < e) ? expf(g_gate[i] - gm) : 0.f;
        __syncthreads();
        int lim = min(256, e - i0);
        for (int k = 0; k < lim; k++) acc += h[(size_t)(i0 + k) * DD + tid] * red[k];
        __syncthreads();
    }
    out[g * DD + tid] = (e > s) ? acc / denom : 0.f;
}

// ---------------- launch ----------------
extern "C" void kernel_launch(void* const* d_in, const int* in_sizes, int n_in,
                              void* d_out, int out_size) {
    const int* x   = (const int*)d_in[0];
    const int* src = (const int*)d_in[1];
    const int* dst = (const int*)d_in[2];
    const int* et  = (const int*)d_in[3];
    const int* seg = (const int*)d_in[4];
    int base = (in_sizes[5] == 1) ? 6 : 5;
    const float* emb    = (const float*)d_in[base + 0];
    const float* Wmsg   = (const float*)d_in[base + 1];
    const float* bmsg   = (const float*)d_in[base + 2];
    const float* w_ih   = (const float*)d_in[base + 3];
    const float* w_hh   = (const float*)d_in[base + 4];
    const float* b_ih   = (const float*)d_in[base + 5];
    const float* b_hh   = (const float*)d_in[base + 6];
    const float* gate_w = (const float*)d_in[base + 7];
    const float* gate_b = (const float*)d_in[base + 8];
    float* out = (float*)d_out;

    cudaFuncSetAttribute(gemm_msg_tc, cudaFuncAttributeMaxDynamicSharedMemorySize, SMEM_BYTES);
    cudaFuncSetAttribute(gemm_bt2_tc, cudaFuncAttributeMaxDynamicSharedMemorySize, SMEM_BYTES);

    float *ph0, *ph1, *pgi, *pgh;
    u32 *pah, *pal, *phh, *phl, *pwihh, *pwihl, *pwhhh, *pwhhl;
    cudaGetSymbolAddress((void**)&ph0, g_h0);
    cudaGetSymbolAddress((void**)&ph1, g_h1);
    cudaGetSymbolAddress((void**)&pgi, g_gi);
    cudaGetSymbolAddress((void**)&pgh, g_gh);
    cudaGetSymbolAddress((void**)&pah, g_ah);
    cudaGetSymbolAddress((void**)&pal, g_al);
    cudaGetSymbolAddress((void**)&phh, g_hsh);
    cudaGetSymbolAddress((void**)&phl, g_hsl);
    cudaGetSymbolAddress((void**)&pwihh, g_wihh);
    cudaGetSymbolAddress((void**)&pwihl, g_wihl);
    cudaGetSymbolAddress((void**)&pwhhh, g_whhh);
    cudaGetSymbolAddress((void**)&pwhhl, g_whhl);

    // CSR build (edges constant across steps)
    const int nb = (BINS + 1023) / 1024;   // 147
    zero_cursor<<<(BINS + 255) / 256, 256>>>();
    hist_kernel<<<(NE + 255) / 256, 256>>>(dst, et);
    scanA<<<nb, 256>>>();
    scanB<<<1, 256>>>(nb);
    scanC<<<nb, 256>>>();
    fill_kernel<<<(NE + 255) / 256, 256>>>(src, dst, et);

    split_weights<<<(NET * DD * DD + 255) / 256, 256>>>(Wmsg, w_ih, w_hh);

    const int elem4 = NN * DD / 4;
    embed_kernel<<<(elem4 + 255) / 256, 256>>>(x, emb, ph0, phh, phl);

    const int rowblk = (NN + BM - 1) / BM;   // 391
    float* hin = ph0;
    float* hout = ph1;
    int side = 0;
    for (int step = 0; step < NSTEPS; step++) {
        u32* hinh = phh + (size_t)side * NN * DD;
        u32* hinl = phl + (size_t)side * NN * DD;
        u32* houth = phh + (size_t)(1 - side) * NN * DD;
        u32* houtl = phl + (size_t)(1 - side) * NN * DD;

        aggregate_kernel<<<(BINS + 7) / 8, 256>>>(hin);
        gemm_msg_tc<<<dim3(rowblk, DD / BN), 256, SMEM_BYTES>>>(bmsg);
        gemm_bt2_tc<<<dim3(rowblk, G3 / BN, 2), 256, SMEM_BYTES>>>(
            pah, pal, pwihh, pwihl, b_ih, pgi,
            hinh, hinl, pwhhh, pwhhl, b_hh, pgh);
        gru_gate<<<(elem4 + 255) / 256, 256>>>(pgi, pgh, hin, hout, houth, houtl);

        float* t = hin; hin = hout; hout = t;
        side = 1 - side;
    }
    gate_kernel<<<(NN * 32 + 255) / 256, 256>>>(hin, gate_w, gate_b);
    pool_kernel<<<NGR, 256>>>(hin, seg, out);
}